// round 10
// baseline (speedup 1.0000x reference)
#include <cuda_runtime.h>
#include <cuda_fp16.h>
#include <math.h>

#define Mdim 2048
#define Ndim 2048
#define MP   2049
#define NP   2049
#define Bdim 4
#define Ddim 256
#define Pdim 8
#define UST  2052   // padded stride for u/v (16B-aligned batch slices)

__device__ float g_u[Bdim * UST];
__device__ float g_v[Bdim * UST];
__device__ float g_dA[(size_t)Bdim * MP * Pdim];
__device__ float g_dB[(size_t)Bdim * MP * Pdim];
__device__ __half g_ER[(size_t)Bdim * Mdim * Ndim];  // half(e^S), row-major
__device__ __half g_EC[(size_t)Bdim * Mdim * Ndim];  // half(e^S), transposed
__device__ unsigned g_count;                          // grid-barrier counter

#define LOG2E_ 1.4426950408889634f
#define LN2_   0.6931471805599453f
#define WSCALE 24.0f   // w' = 2^(v+24); corrected exactly in epilogue

// ---------------------------------------------------------------- utilities

__device__ __forceinline__ float ex2(float x) {
    float y;
    asm("ex2.approx.f32 %0, %1;" : "=f"(y) : "f"(x));
    return y;
}

__device__ __forceinline__ float warp_reduce_sum(float x) {
#pragma unroll
    for (int o = 16; o; o >>= 1) x += __shfl_xor_sync(0xffffffffu, x, o);
    return x;
}

__device__ __forceinline__ float gelu(float x) {
    return 0.5f * x * (1.0f + erff(x * 0.7071067811865476f));
}

__device__ __forceinline__ void ladder5(float t[5], float x) {
#pragma unroll
    for (int i = 0; i < 5; i++) {
        float hi = fmaxf(t[i], x);
        x = fminf(t[i], x);
        t[i] = hi;
    }
}

__device__ __forceinline__ void merge5(float t[5], const float s[5]) {
#pragma unroll
    for (int i = 0; i < 5; i++) ladder5(t, s[i]);
}

__device__ __forceinline__ void top5_merge_shfl(float t[5]) {
#pragma unroll
    for (int o = 16; o; o >>= 1) {
        float p[5];
#pragma unroll
        for (int i = 0; i < 5; i++) p[i] = __shfl_xor_sync(0xffffffffu, t[i], o);
        merge5(t, p);
    }
}

// ---------------------------------------------------------------- smem layouts

struct alignas(16) MlpW {
    float w1t[16 * 64];
    float b1[64], g1[64], be1[64];
    float w2t[64 * 64];
    float b2[64], g2[64], be2[64];
    float w3[64];
    float b3;
    float pad[3];
};
static_assert(sizeof(MlpW) % 16 == 0, "MlpW must be 16B multiple");

struct alignas(16) SmemAll {
    MlpW Wr;
    MlpW Wc;
    float ws[UST];
};
static_assert(offsetof(SmemAll, ws) % 16 == 0, "ws must be 16B aligned");

struct alignas(16) ProjSm {          // aliased over smem during prologue
    float sw[Pdim * Ddim];
    float part[8][32][Pdim];
};

__device__ void load_mlp_weights(MlpW* s,
                                 const float* w1, const float* b1, const float* g1, const float* be1,
                                 const float* w2, const float* b2, const float* g2, const float* be2,
                                 const float* w3, const float* b3,
                                 int tid, int nthreads) {
    for (int i = tid; i < 16 * 64; i += nthreads) {
        int u = i / 16, k = i % 16;
        s->w1t[k * 64 + u] = w1[i];
    }
    for (int i = tid; i < 64 * 64; i += nthreads) {
        int u = i / 64, k = i % 64;
        s->w2t[k * 64 + u] = w2[i];
    }
    for (int i = tid; i < 64; i += nthreads) {
        s->b1[i] = b1[i];  s->g1[i] = g1[i];  s->be1[i] = be1[i];
        s->b2[i] = b2[i];  s->g2[i] = g2[i];  s->be2[i] = be2[i];
        s->w3[i] = w3[i];
    }
    if (tid == 0) s->b3 = b3[0];
}

__device__ float warp_mlp(const MlpW* W, const float f[16], int lane) {
    float a0 = W->b1[lane], a1 = W->b1[lane + 32];
#pragma unroll
    for (int k = 0; k < 16; k++) {
        a0 = fmaf(f[k], W->w1t[k * 64 + lane], a0);
        a1 = fmaf(f[k], W->w1t[k * 64 + 32 + lane], a1);
    }
    float h0 = gelu(a0), h1 = gelu(a1);
    float mu  = warp_reduce_sum(h0 + h1) * (1.0f / 64.0f);
    float d0 = h0 - mu, d1 = h1 - mu;
    float var = warp_reduce_sum(d0 * d0 + d1 * d1) * (1.0f / 64.0f);
    float inv = 1.0f / sqrtf(var + 1e-5f);
    h0 = d0 * inv * W->g1[lane]      + W->be1[lane];
    h1 = d1 * inv * W->g1[lane + 32] + W->be1[lane + 32];

    a0 = W->b2[lane];
    a1 = W->b2[lane + 32];
#pragma unroll
    for (int k = 0; k < 32; k++) {
        float x0 = __shfl_sync(0xffffffffu, h0, k);
        float x1 = __shfl_sync(0xffffffffu, h1, k);
        a0 = fmaf(x0, W->w2t[k * 64 + lane], a0);
        a0 = fmaf(x1, W->w2t[(k + 32) * 64 + lane], a0);
        a1 = fmaf(x0, W->w2t[k * 64 + 32 + lane], a1);
        a1 = fmaf(x1, W->w2t[(k + 32) * 64 + 32 + lane], a1);
    }
    h0 = gelu(a0); h1 = gelu(a1);
    mu  = warp_reduce_sum(h0 + h1) * (1.0f / 64.0f);
    d0 = h0 - mu; d1 = h1 - mu;
    var = warp_reduce_sum(d0 * d0 + d1 * d1) * (1.0f / 64.0f);
    inv = 1.0f / sqrtf(var + 1e-5f);
    h0 = d0 * inv * W->g2[lane]      + W->be2[lane];
    h1 = d1 * inv * W->g2[lane + 32] + W->be2[lane + 32];

    float out = h0 * W->w3[lane] + h1 * W->w3[lane + 32];
    out = warp_reduce_sum(out) + W->b3;
    return out;
}

// software grid barrier #k: waits until all gridDim.x blocks arrived
__device__ __forceinline__ void grid_barrier(int k) {
    __syncthreads();
    if (threadIdx.x == 0) {
        __threadfence();
        atomicAdd(&g_count, 1u);
        unsigned target = (unsigned)(k + 1) * gridDim.x;
        while (*((volatile unsigned*)&g_count) < target) { __nanosleep(64); }
        __threadfence();
    }
    __syncthreads();
}

// ---------------------------------------------------------------- init (counter only)

__global__ void init_kernel() {
    g_count = 0u;
}

// ---------------------------------------------------------------- persistent everything

// one row's sweep + MLP update (linear domain)
__device__ void row_work(const MlpW* W, const __half* Emat, const float* ws,
                         float EA, const float* dfeat, float* uout,
                         int m, int lane) {
    bool dust = (m == Mdim);
    const uint2* erow = reinterpret_cast<const uint2*>(Emat + (size_t)m * Ndim);
    const float4* ws4 = reinterpret_cast<const float4*>(ws);

    float s0 = 0.0f, s1 = 0.0f, s2 = 0.0f, s3 = 0.0f;
    float t5[5] = {-INFINITY, -INFINITY, -INFINITY, -INFINITY, -INFINITY};

    if (!dust) {
#pragma unroll
        for (int i = 0; i < 8; i++) {
            uint2 ea = erow[i * 64 + lane];
            uint2 eb = erow[i * 64 + 32 + lane];
            float4 wa = ws4[i * 64 + lane];
            float4 wb = ws4[i * 64 + 32 + lane];
            float2 gA = __half22float2(*reinterpret_cast<__half2*>(&ea.x));
            float2 gB = __half22float2(*reinterpret_cast<__half2*>(&ea.y));
            float2 gC = __half22float2(*reinterpret_cast<__half2*>(&eb.x));
            float2 gD = __half22float2(*reinterpret_cast<__half2*>(&eb.y));
            float p0 = gA.x * wa.x, p1 = gA.y * wa.y;
            float p2 = gB.x * wa.z, p3 = gB.y * wa.w;
            float p4 = gC.x * wb.x, p5 = gC.y * wb.y;
            float p6 = gD.x * wb.z, p7 = gD.y * wb.w;
            s0 += p0; s1 += p1; s2 += p2; s3 += p3;
            s0 += p4; s1 += p5; s2 += p6; s3 += p7;
            float gm = fmaxf(fmaxf(fmaxf(p0, p1), fmaxf(p2, p3)),
                             fmaxf(fmaxf(p4, p5), fmaxf(p6, p7)));
            ladder5(t5, gm);
        }
    } else {
#pragma unroll
        for (int i = 0; i < 8; i++) {
            float4 wa = ws4[i * 64 + lane];
            float4 wb = ws4[i * 64 + 32 + lane];
            float p0 = EA * wa.x, p1 = EA * wa.y, p2 = EA * wa.z, p3 = EA * wa.w;
            float p4 = EA * wb.x, p5 = EA * wb.y, p6 = EA * wb.z, p7 = EA * wb.w;
            s0 += p0; s1 += p1; s2 += p2; s3 += p3;
            s0 += p4; s1 += p5; s2 += p6; s3 += p7;
            float gm = fmaxf(fmaxf(fmaxf(p0, p1), fmaxf(p2, p3)),
                             fmaxf(fmaxf(p4, p5), fmaxf(p6, p7)));
            ladder5(t5, gm);
        }
    }
    if (lane == 0) {
        float p = EA * ws[Ndim];
        s0 += p;
        ladder5(t5, p);
    }

    float tot = warp_reduce_sum((s0 + s1) + (s2 + s3));
    top5_merge_shfl(t5);

    float lse = __log2f(tot) - WSCALE;
    float l2mu = dust ? -1.0f : -12.0f;
    float un = l2mu - lse;

    float f[16];
    f[0] = l2mu * LN2_;
    f[1] = un * LN2_;
    f[2] = 0.0f;
    f[3] = __logf(__fdividef(t5[0], t5[1]));
    f[4] = __logf(__fdividef(t5[0], t5[2]));
    f[5] = __logf(__fdividef(t5[0], t5[3]));
    f[6] = __logf(__fdividef(t5[0], t5[4]));
    f[7] = __logf(__fdividef(tot, t5[0]));
    const float* da = dfeat + (size_t)m * Pdim;
#pragma unroll
    for (int p = 0; p < 8; p++) f[8 + p] = da[p];

    float delta = warp_mlp(W, f, lane);
    if (lane == 0) uout[m] = un + delta * LOG2E_;
}

__global__ __launch_bounds__(256) void sink_all(
    const float* __restrict__ scores, const float* __restrict__ alpha,
    const float* __restrict__ mdesc0, const float* __restrict__ pA_w, const float* __restrict__ pA_b,
    const float* __restrict__ mdesc1, const float* __restrict__ pB_w, const float* __restrict__ pB_b,
    const float* rw1, const float* rb1, const float* rg1, const float* rbe1,
    const float* rw2, const float* rb2, const float* rg2, const float* rbe2,
    const float* rw3, const float* rb3,
    const float* cw1, const float* cb1, const float* cg1, const float* cbe1,
    const float* cw2, const float* cb2, const float* cg2, const float* cbe2,
    const float* cw3, const float* cb3,
    float* __restrict__ out) {
    extern __shared__ __align__(16) unsigned char smem_raw[];
    SmemAll* S = reinterpret_cast<SmemAll*>(smem_raw);
    float (*tile)[65] = reinterpret_cast<float (*)[65]>(smem_raw);
    ProjSm* PS = reinterpret_cast<ProjSm*>(smem_raw);

    int tid = threadIdx.x;
    int warp = tid >> 5, lane = tid & 31;
    int b = blockIdx.x & 3;          // batch bound to block (for sweep phases)
    int blk = blockIdx.x >> 2;
    int nb = gridDim.x >> 2;

    float alphaL = alpha[0] * LOG2E_;
    float EA = ex2(alphaL);

    // ---------------- prologue A: build ER + EC (e^S, row-major + transposed)
    {
        int r = tid >> 4;            // 0..15
        int c4 = (tid & 15) * 4;     // 0..60
        for (int t = blockIdx.x; t < Bdim * 32 * 32; t += gridDim.x) {
            int pb_ = t >> 10;
            int rem = t & 1023;
            int tr0 = (rem >> 5) * 64;
            int tc0 = (rem & 31) * 64;
            __syncthreads();        // protect smem tile reuse across tasks
            const float* sp = scores + ((size_t)pb_ * Mdim + tr0) * Ndim + tc0;
            __half* eR = g_ER + ((size_t)pb_ * Mdim + tr0) * Ndim + tc0;
#pragma unroll
            for (int i = 0; i < 4; i++) {
                int row = r + i * 16;
                float4 s = *reinterpret_cast<const float4*>(sp + (size_t)row * Ndim + c4);
                float e0 = ex2(s.x * LOG2E_);
                float e1 = ex2(s.y * LOG2E_);
                float e2 = ex2(s.z * LOG2E_);
                float e3 = ex2(s.w * LOG2E_);
                tile[row][c4 + 0] = e0;
                tile[row][c4 + 1] = e1;
                tile[row][c4 + 2] = e2;
                tile[row][c4 + 3] = e3;
                __half2 h01 = __floats2half2_rn(e0, e1);
                __half2 h23 = __floats2half2_rn(e2, e3);
                uint2 pk;
                pk.x = *reinterpret_cast<unsigned*>(&h01);
                pk.y = *reinterpret_cast<unsigned*>(&h23);
                *reinterpret_cast<uint2*>(eR + (size_t)row * Ndim + c4) = pk;
            }
            __syncthreads();
            __half* eC = g_EC + ((size_t)pb_ * Ndim + tc0) * Mdim + tr0;
#pragma unroll
            for (int i = 0; i < 4; i++) {
                int row = r + i * 16;
                __half2 h01 = __floats2half2_rn(tile[c4 + 0][row], tile[c4 + 1][row]);
                __half2 h23 = __floats2half2_rn(tile[c4 + 2][row], tile[c4 + 3][row]);
                uint2 pk;
                pk.x = *reinterpret_cast<unsigned*>(&h01);
                pk.y = *reinterpret_cast<unsigned*>(&h23);
                *reinterpret_cast<uint2*>(eC + (size_t)row * Mdim + c4) = pk;
            }
        }
    }

    // ---------------- prologue B: descriptor projections (512 tasks of 32 m)
    {
        for (int t = blockIdx.x; t < 512; t += gridDim.x) {
            int which = t >> 8;
            int rem = t & 255;
            int pb_ = rem >> 6;
            int m0 = (rem & 63) * 32;
            const float* mdesc = which ? mdesc1 : mdesc0;
            const float* pw = which ? pB_w : pA_w;
            const float* pbias = which ? pB_b : pA_b;
            float* dOut = which ? g_dB : g_dA;

            __syncthreads();
            for (int i = tid; i < Pdim * Ddim; i += 256) PS->sw[i] = pw[i];
            __syncthreads();

            int dg = tid >> 5;
            int ml = tid & 31;
            float acc[Pdim];
#pragma unroll
            for (int p = 0; p < Pdim; p++) acc[p] = 0.0f;
            const float* base = mdesc + (size_t)pb_ * Ddim * Mdim + m0 + ml;
#pragma unroll 4
            for (int dd = 0; dd < 32; dd++) {
                int d = dg * 32 + dd;
                float val = base[(size_t)d * Mdim];
#pragma unroll
                for (int p = 0; p < Pdim; p++) acc[p] = fmaf(val, PS->sw[p * Ddim + d], acc[p]);
            }
#pragma unroll
            for (int p = 0; p < Pdim; p++) PS->part[dg][ml][p] = acc[p];
            __syncthreads();

            int m2 = tid >> 3, p2 = tid & 7;
            float sum = pbias[p2];
#pragma unroll
            for (int g = 0; g < 8; g++) sum += PS->part[g][m2][p2];
            dOut[((size_t)pb_ * MP + m0 + m2) * Pdim + p2] = sum;
        }
        // dustbin descriptor rows = 0
        if (blockIdx.x == 0 && tid < Bdim * Pdim) {
            int bb = tid >> 3, p = tid & 7;
            g_dA[((size_t)bb * MP + Mdim) * Pdim + p] = 0.0f;
            g_dB[((size_t)bb * MP + Mdim) * Pdim + p] = 0.0f;
        }
    }

    // ---------------- load MLP weights (after last aliased smem use)
    __syncthreads();
    load_mlp_weights(&S->Wr, rw1, rb1, rg1, rbe1, rw2, rb2, rg2, rbe2, rw3, rb3, tid, 256);
    load_mlp_weights(&S->Wc, cw1, cb1, cg1, cbe1, cw2, cb2, cg2, cbe2, cw3, cb3, tid, 256);

    int bar = 0;
    grid_barrier(bar++);   // prologue complete chip-wide

    // ---------------- 6 Sinkhorn half-steps
    for (int it = 0; it < 3; it++) {
#pragma unroll
        for (int axis = 0; axis < 2; axis++) {
            if (it != 0 || axis != 0) grid_barrier(bar++);
            const float* vin  = (axis == 0 ? g_v : g_u) + b * UST;
            float*       uout = (axis == 0 ? g_u : g_v) + b * UST;
            const float* dfeat = (axis == 0 ? g_dA : g_dB) + (size_t)b * MP * Pdim;
            const __half* Emat = (axis == 0 ? g_ER : g_EC) + (size_t)b * Mdim * Ndim;
            const MlpW* W = (axis == 0) ? &S->Wr : &S->Wc;

            if (it == 0 && axis == 0) {
                float w0 = ex2(WSCALE);   // v == 0 on first pass
                for (int i = tid; i < UST; i += 256) S->ws[i] = w0;
            } else {
                for (int i = tid; i < UST; i += 256) S->ws[i] = ex2(vin[i] + WSCALE);
            }
            __syncthreads();

            for (int m = blk * 8 + warp; m < MP; m += nb * 8)
                row_work(W, Emat, S->ws, EA, dfeat, uout, m, lane);
        }
    }

    // ---------------- output phase
    grid_barrier(bar++);
    for (int i = tid; i < UST; i += 256) S->ws[i] = g_v[b * UST + i];  // raw v
    __syncthreads();
    const float* sv = S->ws;

    for (int m = blk * 8 + warp; m < MP; m += nb * 8) {
        float um = g_u[b * UST + m] + 12.0f;
        float* orow = out + ((size_t)b * MP + m) * NP;
        if (m < Mdim) {
            const uint2* erow = reinterpret_cast<const uint2*>(g_ER + ((size_t)b * Mdim + m) * Ndim);
#pragma unroll 2
            for (int i = 0; i < 8; i++) {
                uint2 ea = erow[i * 64 + lane];
                uint2 eb = erow[i * 64 + 32 + lane];
                float2 gA = __half22float2(*reinterpret_cast<__half2*>(&ea.x));
                float2 gB = __half22float2(*reinterpret_cast<__half2*>(&ea.y));
                float2 gC = __half22float2(*reinterpret_cast<__half2*>(&eb.x));
                float2 gD = __half22float2(*reinterpret_cast<__half2*>(&eb.y));
                int n0 = i * 256 + lane * 4;
                int n1 = n0 + 128;
                orow[n0 + 0] = __log2f(gA.x) + um + sv[n0 + 0];
                orow[n0 + 1] = __log2f(gA.y) + um + sv[n0 + 1];
                orow[n0 + 2] = __log2f(gB.x) + um + sv[n0 + 2];
                orow[n0 + 3] = __log2f(gB.y) + um + sv[n0 + 3];
                orow[n1 + 0] = __log2f(gC.x) + um + sv[n1 + 0];
                orow[n1 + 1] = __log2f(gC.y) + um + sv[n1 + 1];
                orow[n1 + 2] = __log2f(gD.x) + um + sv[n1 + 2];
                orow[n1 + 3] = __log2f(gD.y) + um + sv[n1 + 3];
            }
            if (lane == 0) orow[Ndim] = alphaL + um + sv[Ndim];
        } else {
            for (int k = 0; k < 65; k++) {
                int n = k * 32 + lane;
                if (n < NP) orow[n] = alphaL + um + sv[n];
            }
        }
    }
}

// ---------------------------------------------------------------- launch

extern "C" void kernel_launch(void* const* d_in, const int* in_sizes, int n_in,
                              void* d_out, int out_size) {
    const float* scores = (const float*)d_in[0];
    const float* alpha  = (const float*)d_in[1];
    const float* mdesc0 = (const float*)d_in[2];
    const float* mdesc1 = (const float*)d_in[3];
    const float* pA_w   = (const float*)d_in[4];
    const float* pA_b   = (const float*)d_in[5];
    const float* pB_w   = (const float*)d_in[6];
    const float* pB_b   = (const float*)d_in[7];
    const float* rW[10];
    const float* cW[10];
    for (int i = 0; i < 10; i++) rW[i] = (const float*)d_in[8 + i];
    for (int i = 0; i < 10; i++) cW[i] = (const float*)d_in[18 + i];
    float* out = (float*)d_out;

    init_kernel<<<1, 1>>>();

    int smem_bytes = (int)sizeof(SmemAll);
    cudaFuncSetAttribute(sink_all, cudaFuncAttributeMaxDynamicSharedMemorySize, smem_bytes);
    int occ = 0;
    cudaOccupancyMaxActiveBlocksPerMultiprocessor(&occ, sink_all, 256, smem_bytes);
    if (occ < 1) occ = 1;
    int smcount = 0;
    cudaDeviceGetAttribute(&smcount, cudaDevAttrMultiProcessorCount, 0);
    if (smcount < 1) smcount = 148;
    int grid = (smcount * occ / 4) * 4;
    if (grid < 4) grid = 4;

    sink_all<<<grid, 256, smem_bytes>>>(scores, alpha,
        mdesc0, pA_w, pA_b, mdesc1, pB_w, pB_b,
        rW[0], rW[1], rW[2], rW[3], rW[4], rW[5], rW[6], rW[7], rW[8], rW[9],
        cW[0], cW[1], cW[2], cW[3], cW[4], cW[5], cW[6], cW[7], cW[8], cW[9],
        out);
}

// round 12
// speedup vs baseline: 1.1953x; 1.1953x over previous
#include <cuda_runtime.h>
#include <cuda_fp16.h>
#include <math.h>

#define Mdim 2048
#define Ndim 2048
#define MP   2049
#define NP   2049
#define Bdim 4
#define Ddim 256
#define Pdim 8
#define UST  2052   // padded stride for u/v (16B-aligned batch slices)

__device__ float g_u[Bdim * UST];
__device__ float g_v[Bdim * UST];
__device__ float g_dA[(size_t)Bdim * MP * Pdim];
__device__ float g_dB[(size_t)Bdim * MP * Pdim];
__device__ __half g_ER[(size_t)Bdim * Mdim * Ndim];  // half(e^S), row-major
__device__ __half g_EC[(size_t)Bdim * Mdim * Ndim];  // half(e^S), transposed
__device__ unsigned g_count;                          // grid-barrier counter

#define LOG2E_ 1.4426950408889634f
#define LN2_   0.6931471805599453f
#define WSCALE 24.0f   // w' = 2^(v+24); corrected exactly in epilogue

// ---------------------------------------------------------------- utilities

__device__ __forceinline__ float ex2(float x) {
    float y;
    asm("ex2.approx.f32 %0, %1;" : "=f"(y) : "f"(x));
    return y;
}

__device__ __forceinline__ float warp_reduce_sum(float x) {
#pragma unroll
    for (int o = 16; o; o >>= 1) x += __shfl_xor_sync(0xffffffffu, x, o);
    return x;
}

__device__ __forceinline__ float gelu(float x) {
    return 0.5f * x * (1.0f + erff(x * 0.7071067811865476f));
}

__device__ __forceinline__ void ladder5(float t[5], float x) {
#pragma unroll
    for (int i = 0; i < 5; i++) {
        float hi = fmaxf(t[i], x);
        x = fminf(t[i], x);
        t[i] = hi;
    }
}

__device__ __forceinline__ void merge5(float t[5], const float s[5]) {
#pragma unroll
    for (int i = 0; i < 5; i++) ladder5(t, s[i]);
}

__device__ __forceinline__ void top5_merge_shfl(float t[5]) {
#pragma unroll
    for (int o = 16; o; o >>= 1) {
        float p[5];
#pragma unroll
        for (int i = 0; i < 5; i++) p[i] = __shfl_xor_sync(0xffffffffu, t[i], o);
        merge5(t, p);
    }
}

// ---------------------------------------------------------------- smem layouts

struct alignas(16) MlpW {
    float w1t[16 * 64];
    float b1[64], g1[64], be1[64];
    float w2t[64 * 64];
    float b2[64], g2[64], be2[64];
    float w3[64];
    float b3;
    float pad[3];
};
static_assert(sizeof(MlpW) % 16 == 0, "MlpW must be 16B multiple");

struct alignas(16) SmemAll {
    MlpW W;              // single buffer, reloaded per phase
    float ws[UST];
};
static_assert(offsetof(SmemAll, ws) % 16 == 0, "ws must be 16B aligned");

__device__ void load_mlp_weights(MlpW* s,
                                 const float* w1, const float* b1, const float* g1, const float* be1,
                                 const float* w2, const float* b2, const float* g2, const float* be2,
                                 const float* w3, const float* b3,
                                 int tid, int nthreads) {
    for (int i = tid; i < 16 * 64; i += nthreads) {
        int u = i / 16, k = i % 16;
        s->w1t[k * 64 + u] = w1[i];
    }
    for (int i = tid; i < 64 * 64; i += nthreads) {
        int u = i / 64, k = i % 64;
        s->w2t[k * 64 + u] = w2[i];
    }
    for (int i = tid; i < 64; i += nthreads) {
        s->b1[i] = b1[i];  s->g1[i] = g1[i];  s->be1[i] = be1[i];
        s->b2[i] = b2[i];  s->g2[i] = g2[i];  s->be2[i] = be2[i];
        s->w3[i] = w3[i];
    }
    if (tid == 0) s->b3 = b3[0];
}

__device__ float warp_mlp(const MlpW* W, const float f[16], int lane) {
    float a0 = W->b1[lane], a1 = W->b1[lane + 32];
#pragma unroll
    for (int k = 0; k < 16; k++) {
        a0 = fmaf(f[k], W->w1t[k * 64 + lane], a0);
        a1 = fmaf(f[k], W->w1t[k * 64 + 32 + lane], a1);
    }
    float h0 = gelu(a0), h1 = gelu(a1);
    float mu  = warp_reduce_sum(h0 + h1) * (1.0f / 64.0f);
    float d0 = h0 - mu, d1 = h1 - mu;
    float var = warp_reduce_sum(d0 * d0 + d1 * d1) * (1.0f / 64.0f);
    float inv = 1.0f / sqrtf(var + 1e-5f);
    h0 = d0 * inv * W->g1[lane]      + W->be1[lane];
    h1 = d1 * inv * W->g1[lane + 32] + W->be1[lane + 32];

    a0 = W->b2[lane];
    a1 = W->b2[lane + 32];
#pragma unroll
    for (int k = 0; k < 32; k++) {
        float x0 = __shfl_sync(0xffffffffu, h0, k);
        float x1 = __shfl_sync(0xffffffffu, h1, k);
        a0 = fmaf(x0, W->w2t[k * 64 + lane], a0);
        a0 = fmaf(x1, W->w2t[(k + 32) * 64 + lane], a0);
        a1 = fmaf(x0, W->w2t[k * 64 + 32 + lane], a1);
        a1 = fmaf(x1, W->w2t[(k + 32) * 64 + 32 + lane], a1);
    }
    h0 = gelu(a0); h1 = gelu(a1);
    mu  = warp_reduce_sum(h0 + h1) * (1.0f / 64.0f);
    d0 = h0 - mu; d1 = h1 - mu;
    var = warp_reduce_sum(d0 * d0 + d1 * d1) * (1.0f / 64.0f);
    inv = 1.0f / sqrtf(var + 1e-5f);
    h0 = d0 * inv * W->g2[lane]      + W->be2[lane];
    h1 = d1 * inv * W->g2[lane + 32] + W->be2[lane + 32];

    float out = h0 * W->w3[lane] + h1 * W->w3[lane + 32];
    out = warp_reduce_sum(out) + W->b3;
    return out;
}

// software grid barrier #k: waits until all gridDim.x blocks arrived
__device__ __forceinline__ void grid_barrier(int k) {
    __syncthreads();
    if (threadIdx.x == 0) {
        __threadfence();
        atomicAdd(&g_count, 1u);
        unsigned target = (unsigned)(k + 1) * gridDim.x;
        while (*((volatile unsigned*)&g_count) < target) { __nanosleep(64); }
        __threadfence();
    }
    __syncthreads();
}

// ---------------------------------------------------------------- prologue kernels

__global__ void init_kernel() {
    int i = blockIdx.x * 512 + threadIdx.x;
    if (i == 0) g_count = 0u;
    if (i < Bdim * UST) { g_v[i] = 0.0f; g_u[i] = 0.0f; }
    if (i < Bdim * Pdim) {
        int b = i >> 3, p = i & 7;
        g_dA[((size_t)b * MP + Mdim) * Pdim + p] = 0.0f;
        g_dB[((size_t)b * MP + Mdim) * Pdim + p] = 0.0f;
    }
}

// scores -> half(e^S): row-major (ER) and transposed (EC), 64x64 tiles.
__global__ __launch_bounds__(256) void prep_kernel(const float* __restrict__ scores) {
    __shared__ float tile[64][65];
    int b = blockIdx.z;
    int tr0 = blockIdx.y * 64;
    int tc0 = blockIdx.x * 64;
    int t = threadIdx.x;
    int r = t >> 4;
    int c4 = (t & 15) * 4;

    const float* sp = scores + ((size_t)b * Mdim + tr0) * Ndim + tc0;
    __half* eR = g_ER + ((size_t)b * Mdim + tr0) * Ndim + tc0;
#pragma unroll
    for (int i = 0; i < 4; i++) {
        int row = r + i * 16;
        float4 s = *reinterpret_cast<const float4*>(sp + (size_t)row * Ndim + c4);
        float e0 = ex2(s.x * LOG2E_);
        float e1 = ex2(s.y * LOG2E_);
        float e2 = ex2(s.z * LOG2E_);
        float e3 = ex2(s.w * LOG2E_);
        tile[row][c4 + 0] = e0;
        tile[row][c4 + 1] = e1;
        tile[row][c4 + 2] = e2;
        tile[row][c4 + 3] = e3;
        __half2 h01 = __floats2half2_rn(e0, e1);
        __half2 h23 = __floats2half2_rn(e2, e3);
        uint2 pk;
        pk.x = *reinterpret_cast<unsigned*>(&h01);
        pk.y = *reinterpret_cast<unsigned*>(&h23);
        *reinterpret_cast<uint2*>(eR + (size_t)row * Ndim + c4) = pk;
    }
    __syncthreads();
    __half* eC = g_EC + ((size_t)b * Ndim + tc0) * Mdim + tr0;
#pragma unroll
    for (int i = 0; i < 4; i++) {
        int row = r + i * 16;
        __half2 h01 = __floats2half2_rn(tile[c4 + 0][row], tile[c4 + 1][row]);
        __half2 h23 = __floats2half2_rn(tile[c4 + 2][row], tile[c4 + 3][row]);
        uint2 pk;
        pk.x = *reinterpret_cast<unsigned*>(&h01);
        pk.y = *reinterpret_cast<unsigned*>(&h23);
        *reinterpret_cast<uint2*>(eC + (size_t)row * Mdim + c4) = pk;
    }
}

// dOut[b,m,p] = sum_d mdesc[b,d,m] * pw[p,d] + pb[p]
// 512 threads = 64 m x 8 d-groups; grid (32, Bdim).
__global__ __launch_bounds__(512) void proj_kernel(const float* __restrict__ mdesc,
                                                   const float* __restrict__ pw,
                                                   const float* __restrict__ pb,
                                                   int which) {
    __shared__ float sw[Pdim * Ddim];
    __shared__ float part[8][64][Pdim];
    int tid = threadIdx.x, b = blockIdx.y;
    for (int i = tid; i < Pdim * Ddim; i += 512) sw[i] = pw[i];
    __syncthreads();

    int dg = tid >> 6;
    int ml = tid & 63;
    int m0 = blockIdx.x * 64;
    float acc[Pdim];
#pragma unroll
    for (int p = 0; p < Pdim; p++) acc[p] = 0.0f;
    const float* base = mdesc + (size_t)b * Ddim * Mdim + m0 + ml;
#pragma unroll 4
    for (int dd = 0; dd < 32; dd++) {
        int d = dg * 32 + dd;
        float val = base[(size_t)d * Mdim];
#pragma unroll
        for (int p = 0; p < Pdim; p++) acc[p] = fmaf(val, sw[p * Ddim + d], acc[p]);
    }
#pragma unroll
    for (int p = 0; p < Pdim; p++) part[dg][ml][p] = acc[p];
    __syncthreads();

    int m2 = tid >> 3, p2 = tid & 7;
    float sum = pb[p2];
#pragma unroll
    for (int g = 0; g < 8; g++) sum += part[g][m2][p2];
    float* dOut = which ? g_dB : g_dA;
    dOut[((size_t)b * MP + m0 + m2) * Pdim + p2] = sum;
}

// ---------------------------------------------------------------- persistent Sinkhorn

// one row's sweep + MLP update (linear domain), group-of-16 top5
__device__ void row_work(const MlpW* W, const __half* Emat, const float* ws,
                         float EA, const float* dfeat, float* uout,
                         int m, int lane) {
    bool dust = (m == Mdim);
    const uint2* erow = reinterpret_cast<const uint2*>(Emat + (size_t)m * Ndim);
    const float4* ws4 = reinterpret_cast<const float4*>(ws);

    float s0 = 0.0f, s1 = 0.0f, s2 = 0.0f, s3 = 0.0f;
    float t5[5] = {-INFINITY, -INFINITY, -INFINITY, -INFINITY, -INFINITY};

    if (!dust) {
#pragma unroll 2
        for (int i = 0; i < 4; i++) {
            uint2 e0 = erow[i * 128 + lane];
            uint2 e1 = erow[i * 128 + 32 + lane];
            uint2 e2 = erow[i * 128 + 64 + lane];
            uint2 e3 = erow[i * 128 + 96 + lane];
            float4 w0 = ws4[i * 128 + lane];
            float4 w1 = ws4[i * 128 + 32 + lane];
            float4 w2 = ws4[i * 128 + 64 + lane];
            float4 w3 = ws4[i * 128 + 96 + lane];
            float2 a0 = __half22float2(*reinterpret_cast<__half2*>(&e0.x));
            float2 a1 = __half22float2(*reinterpret_cast<__half2*>(&e0.y));
            float2 b0 = __half22float2(*reinterpret_cast<__half2*>(&e1.x));
            float2 b1 = __half22float2(*reinterpret_cast<__half2*>(&e1.y));
            float2 c0 = __half22float2(*reinterpret_cast<__half2*>(&e2.x));
            float2 c1 = __half22float2(*reinterpret_cast<__half2*>(&e2.y));
            float2 d0 = __half22float2(*reinterpret_cast<__half2*>(&e3.x));
            float2 d1 = __half22float2(*reinterpret_cast<__half2*>(&e3.y));
            float p0  = a0.x * w0.x, p1  = a0.y * w0.y, p2  = a1.x * w0.z, p3  = a1.y * w0.w;
            float p4  = b0.x * w1.x, p5  = b0.y * w1.y, p6  = b1.x * w1.z, p7  = b1.y * w1.w;
            float p8  = c0.x * w2.x, p9  = c0.y * w2.y, p10 = c1.x * w2.z, p11 = c1.y * w2.w;
            float p12 = d0.x * w3.x, p13 = d0.y * w3.y, p14 = d1.x * w3.z, p15 = d1.y * w3.w;
            s0 += p0 + p4;  s1 += p1 + p5;  s2 += p2 + p6;  s3 += p3 + p7;
            s0 += p8 + p12; s1 += p9 + p13; s2 += p10 + p14; s3 += p11 + p15;
            float m0_ = fmaxf(fmaxf(p0, p1), fmaxf(p2, p3));
            float m1_ = fmaxf(fmaxf(p4, p5), fmaxf(p6, p7));
            float m2_ = fmaxf(fmaxf(p8, p9), fmaxf(p10, p11));
            float m3_ = fmaxf(fmaxf(p12, p13), fmaxf(p14, p15));
            float gm = fmaxf(fmaxf(m0_, m1_), fmaxf(m2_, m3_));
            ladder5(t5, gm);
        }
    } else {
#pragma unroll 2
        for (int i = 0; i < 4; i++) {
            float4 w0 = ws4[i * 128 + lane];
            float4 w1 = ws4[i * 128 + 32 + lane];
            float4 w2 = ws4[i * 128 + 64 + lane];
            float4 w3 = ws4[i * 128 + 96 + lane];
            float p0  = EA * w0.x, p1  = EA * w0.y, p2  = EA * w0.z, p3  = EA * w0.w;
            float p4  = EA * w1.x, p5  = EA * w1.y, p6  = EA * w1.z, p7  = EA * w1.w;
            float p8  = EA * w2.x, p9  = EA * w2.y, p10 = EA * w2.z, p11 = EA * w2.w;
            float p12 = EA * w3.x, p13 = EA * w3.y, p14 = EA * w3.z, p15 = EA * w3.w;
            s0 += p0 + p4;  s1 += p1 + p5;  s2 += p2 + p6;  s3 += p3 + p7;
            s0 += p8 + p12; s1 += p9 + p13; s2 += p10 + p14; s3 += p11 + p15;
            float m0_ = fmaxf(fmaxf(p0, p1), fmaxf(p2, p3));
            float m1_ = fmaxf(fmaxf(p4, p5), fmaxf(p6, p7));
            float m2_ = fmaxf(fmaxf(p8, p9), fmaxf(p10, p11));
            float m3_ = fmaxf(fmaxf(p12, p13), fmaxf(p14, p15));
            float gm = fmaxf(fmaxf(m0_, m1_), fmaxf(m2_, m3_));
            ladder5(t5, gm);
        }
    }
    if (lane == 0) {
        float p = EA * ws[Ndim];
        s0 += p;
        ladder5(t5, p);
    }

    float tot = warp_reduce_sum((s0 + s1) + (s2 + s3));
    top5_merge_shfl(t5);

    float lse = __log2f(tot) - WSCALE;
    float l2mu = dust ? -1.0f : -12.0f;
    float un = l2mu - lse;

    float f[16];
    f[0] = l2mu * LN2_;
    f[1] = un * LN2_;
    f[2] = 0.0f;
    f[3] = __logf(__fdividef(t5[0], t5[1]));
    f[4] = __logf(__fdividef(t5[0], t5[2]));
    f[5] = __logf(__fdividef(t5[0], t5[3]));
    f[6] = __logf(__fdividef(t5[0], t5[4]));
    f[7] = __logf(__fdividef(tot, t5[0]));
    const float* da = dfeat + (size_t)m * Pdim;
#pragma unroll
    for (int p = 0; p < 8; p++) f[8 + p] = da[p];

    float delta = warp_mlp(W, f, lane);
    if (lane == 0) uout[m] = un + delta * LOG2E_;
}

__global__ __launch_bounds__(256, 5) void sink_all(
    const float* __restrict__ alpha,
    const float* rw1, const float* rb1, const float* rg1, const float* rbe1,
    const float* rw2, const float* rb2, const float* rg2, const float* rbe2,
    const float* rw3, const float* rb3,
    const float* cw1, const float* cb1, const float* cg1, const float* cbe1,
    const float* cw2, const float* cb2, const float* cg2, const float* cbe2,
    const float* cw3, const float* cb3,
    float* __restrict__ out) {
    extern __shared__ __align__(16) unsigned char smem_raw[];
    SmemAll* S = reinterpret_cast<SmemAll*>(smem_raw);

    int tid = threadIdx.x;
    int warp = tid >> 5, lane = tid & 31;
    int b = blockIdx.x & 3;          // batch bound to block
    int blk = blockIdx.x >> 2;
    int nb = gridDim.x >> 2;

    float alphaL = alpha[0] * LOG2E_;
    float EA = ex2(alphaL);

    int bar = 0;
    for (int it = 0; it < 3; it++) {
#pragma unroll
        for (int axis = 0; axis < 2; axis++) {
            if (it != 0 || axis != 0) grid_barrier(bar++);
            const float* vin  = (axis == 0 ? g_v : g_u) + b * UST;
            float*       uout = (axis == 0 ? g_u : g_v) + b * UST;
            const float* dfeat = (axis == 0 ? g_dA : g_dB) + (size_t)b * MP * Pdim;
            const __half* Emat = (axis == 0 ? g_ER : g_EC) + (size_t)b * Mdim * Ndim;

            // reload this phase's MLP weights into the single buffer
            if (axis == 0)
                load_mlp_weights(&S->W, rw1, rb1, rg1, rbe1, rw2, rb2, rg2, rbe2, rw3, rb3, tid, 256);
            else
                load_mlp_weights(&S->W, cw1, cb1, cg1, cbe1, cw2, cb2, cg2, cbe2, cw3, cb3, tid, 256);
            for (int i = tid; i < UST; i += 256) S->ws[i] = ex2(vin[i] + WSCALE);
            __syncthreads();

            for (int m = blk * 8 + warp; m < MP; m += nb * 8)
                row_work(&S->W, Emat, S->ws, EA, dfeat, uout, m, lane);
        }
    }

    // ---- output phase ----
    grid_barrier(bar++);
    for (int i = tid; i < UST; i += 256) S->ws[i] = g_v[b * UST + i];  // raw v
    __syncthreads();
    const float* sv = S->ws;

    for (int m = blk * 8 + warp; m < MP; m += nb * 8) {
        float um = g_u[b * UST + m] + 12.0f;
        float* orow = out + ((size_t)b * MP + m) * NP;
        if (m < Mdim) {
            const uint2* erow = reinterpret_cast<const uint2*>(g_ER + ((size_t)b * Mdim + m) * Ndim);
#pragma unroll 2
            for (int i = 0; i < 8; i++) {
                uint2 ea = erow[i * 64 + lane];
                uint2 eb = erow[i * 64 + 32 + lane];
                float2 gA = __half22float2(*reinterpret_cast<__half2*>(&ea.x));
                float2 gB = __half22float2(*reinterpret_cast<__half2*>(&ea.y));
                float2 gC = __half22float2(*reinterpret_cast<__half2*>(&eb.x));
                float2 gD = __half22float2(*reinterpret_cast<__half2*>(&eb.y));
                int n0 = i * 256 + lane * 4;
                int n1 = n0 + 128;
                orow[n0 + 0] = __log2f(gA.x) + um + sv[n0 + 0];
                orow[n0 + 1] = __log2f(gA.y) + um + sv[n0 + 1];
                orow[n0 + 2] = __log2f(gB.x) + um + sv[n0 + 2];
                orow[n0 + 3] = __log2f(gB.y) + um + sv[n0 + 3];
                orow[n1 + 0] = __log2f(gC.x) + um + sv[n1 + 0];
                orow[n1 + 1] = __log2f(gC.y) + um + sv[n1 + 1];
                orow[n1 + 2] = __log2f(gD.x) + um + sv[n1 + 2];
                orow[n1 + 3] = __log2f(gD.y) + um + sv[n1 + 3];
            }
            if (lane == 0) orow[Ndim] = alphaL + um + sv[Ndim];
        } else {
            for (int k = 0; k < 65; k++) {
                int n = k * 32 + lane;
                if (n < NP) orow[n] = alphaL + um + sv[n];
            }
        }
    }
}

// ---------------------------------------------------------------- launch

extern "C" void kernel_launch(void* const* d_in, const int* in_sizes, int n_in,
                              void* d_out, int out_size) {
    const float* scores = (const float*)d_in[0];
    const float* alpha  = (const float*)d_in[1];
    const float* mdesc0 = (const float*)d_in[2];
    const float* mdesc1 = (const float*)d_in[3];
    const float* pA_w   = (const float*)d_in[4];
    const float* pA_b   = (const float*)d_in[5];
    const float* pB_w   = (const float*)d_in[6];
    const float* pB_b   = (const float*)d_in[7];
    const float* rW[10];
    const float* cW[10];
    for (int i = 0; i < 10; i++) rW[i] = (const float*)d_in[8 + i];
    for (int i = 0; i < 10; i++) cW[i] = (const float*)d_in[18 + i];
    float* out = (float*)d_out;

    init_kernel<<<17, 512>>>();
    prep_kernel<<<dim3(32, 32, Bdim), 256>>>(scores);
    proj_kernel<<<dim3(32, Bdim), 512>>>(mdesc0, pA_w, pA_b, 0);
    proj_kernel<<<dim3(32, Bdim), 512>>>(mdesc1, pB_w, pB_b, 1);

    int smem_bytes = (int)sizeof(SmemAll);
    cudaFuncSetAttribute(sink_all, cudaFuncAttributeMaxDynamicSharedMemorySize, smem_bytes);
    int occ = 0;
    cudaOccupancyMaxActiveBlocksPerMultiprocessor(&occ, sink_all, 256, smem_bytes);
    if (occ < 1) occ = 1;
    int smcount = 0;
    cudaDeviceGetAttribute(&smcount, cudaDevAttrMultiProcessorCount, 0);
    if (smcount < 1) smcount = 148;
    int grid = (smcount * occ / 4) * 4;
    if (grid < 4) grid = 4;

    sink_all<<<grid, 256, smem_bytes>>>(alpha,
        rW[0], rW[1], rW[2], rW[3], rW[4], rW[5], rW[6], rW[7], rW[8], rW[9],
        cW[0], cW[1], cW[2], cW[3], cW[4], cW[5], cW[6], cW[7], cW[8], cW[9],
        out);
}

// round 13
// speedup vs baseline: 1.3404x; 1.1214x over previous
#include <cuda_runtime.h>
#include <cuda_fp16.h>
#include <math.h>

#define Mdim 2048
#define Ndim 2048
#define MP   2049
#define NP   2049
#define Bdim 4
#define Ddim 256
#define Pdim 8
#define UST  2052   // padded stride for u/v (16B-aligned batch slices)

__device__ float g_u[Bdim * UST];
__device__ float g_v[Bdim * UST];
__device__ float g_dA[(size_t)Bdim * MP * Pdim];
__device__ float g_dB[(size_t)Bdim * MP * Pdim];
__device__ __half g_ER[(size_t)Bdim * Mdim * Ndim];  // half(e^S), row-major
__device__ __half g_EC[(size_t)Bdim * Mdim * Ndim];  // half(e^S), transposed
__device__ unsigned g_count;                          // grid-barrier counter

#define LOG2E_ 1.4426950408889634f
#define LN2_   0.6931471805599453f
#define WSCALE 24.0f   // w' = 2^(v+24); corrected exactly in epilogue

// ---------------------------------------------------------------- utilities

__device__ __forceinline__ float ex2(float x) {
    float y;
    asm("ex2.approx.f32 %0, %1;" : "=f"(y) : "f"(x));
    return y;
}

__device__ __forceinline__ float warp_reduce_sum(float x) {
#pragma unroll
    for (int o = 16; o; o >>= 1) x += __shfl_xor_sync(0xffffffffu, x, o);
    return x;
}

__device__ __forceinline__ float gelu(float x) {
    return 0.5f * x * (1.0f + erff(x * 0.7071067811865476f));
}

__device__ __forceinline__ void ladder5(float t[5], float x) {
#pragma unroll
    for (int i = 0; i < 5; i++) {
        float hi = fmaxf(t[i], x);
        x = fminf(t[i], x);
        t[i] = hi;
    }
}

__device__ __forceinline__ void merge5(float t[5], const float s[5]) {
#pragma unroll
    for (int i = 0; i < 5; i++) ladder5(t, s[i]);
}

__device__ __forceinline__ void top5_merge_shfl(float t[5]) {
#pragma unroll
    for (int o = 16; o; o >>= 1) {
        float p[5];
#pragma unroll
        for (int i = 0; i < 5; i++) p[i] = __shfl_xor_sync(0xffffffffu, t[i], o);
        merge5(t, p);
    }
}

// ---------------------------------------------------------------- smem layouts

struct alignas(16) MlpW {
    float w1t[16 * 64];
    float b1[64], g1[64], be1[64];
    float w2t[64 * 64];
    float b2[64], g2[64], be2[64];
    float w3[64];
    float b3;
    float pad[3];
};
static_assert(sizeof(MlpW) % 16 == 0, "MlpW must be 16B multiple");

struct alignas(16) SmemAll {
    MlpW Wr;
    MlpW Wc;
    float ws[UST];
};
static_assert(offsetof(SmemAll, ws) % 16 == 0, "ws must be 16B aligned");

__device__ void load_mlp_weights(MlpW* s,
                                 const float* w1, const float* b1, const float* g1, const float* be1,
                                 const float* w2, const float* b2, const float* g2, const float* be2,
                                 const float* w3, const float* b3,
                                 int tid, int nthreads) {
    for (int i = tid; i < 16 * 64; i += nthreads) {
        int u = i / 16, k = i % 16;
        s->w1t[k * 64 + u] = w1[i];
    }
    for (int i = tid; i < 64 * 64; i += nthreads) {
        int u = i / 64, k = i % 64;
        s->w2t[k * 64 + u] = w2[i];
    }
    for (int i = tid; i < 64; i += nthreads) {
        s->b1[i] = b1[i];  s->g1[i] = g1[i];  s->be1[i] = be1[i];
        s->b2[i] = b2[i];  s->g2[i] = g2[i];  s->be2[i] = be2[i];
        s->w3[i] = w3[i];
    }
    if (tid == 0) s->b3 = b3[0];
}

// single-row MLP (used for remainder rows)
__device__ float warp_mlp(const MlpW* W, const float f[16], int lane) {
    float a0 = W->b1[lane], a1 = W->b1[lane + 32];
#pragma unroll
    for (int k = 0; k < 16; k++) {
        a0 = fmaf(f[k], W->w1t[k * 64 + lane], a0);
        a1 = fmaf(f[k], W->w1t[k * 64 + 32 + lane], a1);
    }
    float h0 = gelu(a0), h1 = gelu(a1);
    float mu  = warp_reduce_sum(h0 + h1) * (1.0f / 64.0f);
    float d0 = h0 - mu, d1 = h1 - mu;
    float var = warp_reduce_sum(d0 * d0 + d1 * d1) * (1.0f / 64.0f);
    float inv = 1.0f / sqrtf(var + 1e-5f);
    h0 = d0 * inv * W->g1[lane]      + W->be1[lane];
    h1 = d1 * inv * W->g1[lane + 32] + W->be1[lane + 32];

    a0 = W->b2[lane];
    a1 = W->b2[lane + 32];
#pragma unroll
    for (int k = 0; k < 32; k++) {
        float x0 = __shfl_sync(0xffffffffu, h0, k);
        float x1 = __shfl_sync(0xffffffffu, h1, k);
        a0 = fmaf(x0, W->w2t[k * 64 + lane], a0);
        a0 = fmaf(x1, W->w2t[(k + 32) * 64 + lane], a0);
        a1 = fmaf(x0, W->w2t[k * 64 + 32 + lane], a1);
        a1 = fmaf(x1, W->w2t[(k + 32) * 64 + 32 + lane], a1);
    }
    h0 = gelu(a0); h1 = gelu(a1);
    mu  = warp_reduce_sum(h0 + h1) * (1.0f / 64.0f);
    d0 = h0 - mu; d1 = h1 - mu;
    var = warp_reduce_sum(d0 * d0 + d1 * d1) * (1.0f / 64.0f);
    inv = 1.0f / sqrtf(var + 1e-5f);
    h0 = d0 * inv * W->g2[lane]      + W->be2[lane];
    h1 = d1 * inv * W->g2[lane + 32] + W->be2[lane + 32];

    float out = h0 * W->w3[lane] + h1 * W->w3[lane + 32];
    out = warp_reduce_sum(out) + W->b3;
    return out;
}

// dual-row MLP: shares weight loads + loop overhead between two rows
__device__ void warp_mlp2(const MlpW* W, const float f0[16], const float f1[16],
                          int lane, float* o0, float* o1) {
    float a0 = W->b1[lane], a1 = W->b1[lane + 32];
    float c0 = a0, c1 = a1;
#pragma unroll
    for (int k = 0; k < 16; k++) {
        float w0 = W->w1t[k * 64 + lane];
        float w1 = W->w1t[k * 64 + 32 + lane];
        a0 = fmaf(f0[k], w0, a0);  a1 = fmaf(f0[k], w1, a1);
        c0 = fmaf(f1[k], w0, c0);  c1 = fmaf(f1[k], w1, c1);
    }
    float h0 = gelu(a0), h1 = gelu(a1);
    float j0 = gelu(c0), j1 = gelu(c1);
    float mu0 = warp_reduce_sum(h0 + h1) * (1.0f / 64.0f);
    float mu1 = warp_reduce_sum(j0 + j1) * (1.0f / 64.0f);
    float dh0 = h0 - mu0, dh1 = h1 - mu0;
    float dj0 = j0 - mu1, dj1 = j1 - mu1;
    float v0 = warp_reduce_sum(dh0 * dh0 + dh1 * dh1) * (1.0f / 64.0f);
    float v1 = warp_reduce_sum(dj0 * dj0 + dj1 * dj1) * (1.0f / 64.0f);
    float i0 = 1.0f / sqrtf(v0 + 1e-5f);
    float i1 = 1.0f / sqrtf(v1 + 1e-5f);
    float g0 = W->g1[lane], g1v = W->g1[lane + 32];
    float e0 = W->be1[lane], e1 = W->be1[lane + 32];
    h0 = dh0 * i0 * g0 + e0;  h1 = dh1 * i0 * g1v + e1;
    j0 = dj0 * i1 * g0 + e0;  j1 = dj1 * i1 * g1v + e1;

    a0 = W->b2[lane];  a1 = W->b2[lane + 32];
    c0 = a0;  c1 = a1;
#pragma unroll
    for (int k = 0; k < 32; k++) {
        float x0 = __shfl_sync(0xffffffffu, h0, k);
        float x1 = __shfl_sync(0xffffffffu, h1, k);
        float y0 = __shfl_sync(0xffffffffu, j0, k);
        float y1 = __shfl_sync(0xffffffffu, j1, k);
        float w00 = W->w2t[k * 64 + lane];
        float w01 = W->w2t[(k + 32) * 64 + lane];
        float w10 = W->w2t[k * 64 + 32 + lane];
        float w11 = W->w2t[(k + 32) * 64 + 32 + lane];
        a0 = fmaf(x0, w00, a0);  a0 = fmaf(x1, w01, a0);
        a1 = fmaf(x0, w10, a1);  a1 = fmaf(x1, w11, a1);
        c0 = fmaf(y0, w00, c0);  c0 = fmaf(y1, w01, c0);
        c1 = fmaf(y0, w10, c1);  c1 = fmaf(y1, w11, c1);
    }
    h0 = gelu(a0); h1 = gelu(a1);
    j0 = gelu(c0); j1 = gelu(c1);
    mu0 = warp_reduce_sum(h0 + h1) * (1.0f / 64.0f);
    mu1 = warp_reduce_sum(j0 + j1) * (1.0f / 64.0f);
    dh0 = h0 - mu0; dh1 = h1 - mu0;
    dj0 = j0 - mu1; dj1 = j1 - mu1;
    v0 = warp_reduce_sum(dh0 * dh0 + dh1 * dh1) * (1.0f / 64.0f);
    v1 = warp_reduce_sum(dj0 * dj0 + dj1 * dj1) * (1.0f / 64.0f);
    i0 = 1.0f / sqrtf(v0 + 1e-5f);
    i1 = 1.0f / sqrtf(v1 + 1e-5f);
    g0 = W->g2[lane]; g1v = W->g2[lane + 32];
    e0 = W->be2[lane]; e1 = W->be2[lane + 32];
    h0 = dh0 * i0 * g0 + e0;  h1 = dh1 * i0 * g1v + e1;
    j0 = dj0 * i1 * g0 + e0;  j1 = dj1 * i1 * g1v + e1;

    float w30 = W->w3[lane], w31 = W->w3[lane + 32];
    float r0 = warp_reduce_sum(h0 * w30 + h1 * w31) + W->b3;
    float r1 = warp_reduce_sum(j0 * w30 + j1 * w31) + W->b3;
    *o0 = r0;
    *o1 = r1;
}

// software grid barrier #k: waits until all gridDim.x blocks arrived
__device__ __forceinline__ void grid_barrier(int k) {
    __syncthreads();
    if (threadIdx.x == 0) {
        __threadfence();
        atomicAdd(&g_count, 1u);
        unsigned target = (unsigned)(k + 1) * gridDim.x;
        while (*((volatile unsigned*)&g_count) < target) { __nanosleep(64); }
        __threadfence();
    }
    __syncthreads();
}

// ---------------------------------------------------------------- prologue kernels

__global__ void init_kernel() {
    int i = blockIdx.x * 512 + threadIdx.x;
    if (i == 0) g_count = 0u;
    if (i < Bdim * UST) { g_v[i] = 0.0f; g_u[i] = 0.0f; }
    if (i < Bdim * Pdim) {
        int b = i >> 3, p = i & 7;
        g_dA[((size_t)b * MP + Mdim) * Pdim + p] = 0.0f;
        g_dB[((size_t)b * MP + Mdim) * Pdim + p] = 0.0f;
    }
}

// scores -> half(e^S): row-major (ER) and transposed (EC), 64x64 tiles.
__global__ __launch_bounds__(256) void prep_kernel(const float* __restrict__ scores) {
    __shared__ float tile[64][65];
    int b = blockIdx.z;
    int tr0 = blockIdx.y * 64;
    int tc0 = blockIdx.x * 64;
    int t = threadIdx.x;
    int r = t >> 4;
    int c4 = (t & 15) * 4;

    const float* sp = scores + ((size_t)b * Mdim + tr0) * Ndim + tc0;
    __half* eR = g_ER + ((size_t)b * Mdim + tr0) * Ndim + tc0;
#pragma unroll
    for (int i = 0; i < 4; i++) {
        int row = r + i * 16;
        float4 s = *reinterpret_cast<const float4*>(sp + (size_t)row * Ndim + c4);
        float e0 = ex2(s.x * LOG2E_);
        float e1 = ex2(s.y * LOG2E_);
        float e2 = ex2(s.z * LOG2E_);
        float e3 = ex2(s.w * LOG2E_);
        tile[row][c4 + 0] = e0;
        tile[row][c4 + 1] = e1;
        tile[row][c4 + 2] = e2;
        tile[row][c4 + 3] = e3;
        __half2 h01 = __floats2half2_rn(e0, e1);
        __half2 h23 = __floats2half2_rn(e2, e3);
        uint2 pk;
        pk.x = *reinterpret_cast<unsigned*>(&h01);
        pk.y = *reinterpret_cast<unsigned*>(&h23);
        *reinterpret_cast<uint2*>(eR + (size_t)row * Ndim + c4) = pk;
    }
    __syncthreads();
    __half* eC = g_EC + ((size_t)b * Ndim + tc0) * Mdim + tr0;
#pragma unroll
    for (int i = 0; i < 4; i++) {
        int row = r + i * 16;
        __half2 h01 = __floats2half2_rn(tile[c4 + 0][row], tile[c4 + 1][row]);
        __half2 h23 = __floats2half2_rn(tile[c4 + 2][row], tile[c4 + 3][row]);
        uint2 pk;
        pk.x = *reinterpret_cast<unsigned*>(&h01);
        pk.y = *reinterpret_cast<unsigned*>(&h23);
        *reinterpret_cast<uint2*>(eC + (size_t)row * Mdim + c4) = pk;
    }
}

// Both projections in ONE launch: blockIdx.z selects A/B.
// 512 threads = 64 m x 8 d-groups; grid (32, Bdim, 2).
__global__ __launch_bounds__(512) void proj_kernel(
    const float* __restrict__ mdesc0, const float* __restrict__ pA_w, const float* __restrict__ pA_b,
    const float* __restrict__ mdesc1, const float* __restrict__ pB_w, const float* __restrict__ pB_b) {
    __shared__ float sw[Pdim * Ddim];
    __shared__ float part[8][64][Pdim];
    int tid = threadIdx.x, b = blockIdx.y;
    int which = blockIdx.z;
    const float* mdesc = which ? mdesc1 : mdesc0;
    const float* pw = which ? pB_w : pA_w;
    const float* pb = which ? pB_b : pA_b;
    for (int i = tid; i < Pdim * Ddim; i += 512) sw[i] = pw[i];
    __syncthreads();

    int dg = tid >> 6;
    int ml = tid & 63;
    int m0 = blockIdx.x * 64;
    float acc[Pdim];
#pragma unroll
    for (int p = 0; p < Pdim; p++) acc[p] = 0.0f;
    const float* base = mdesc + (size_t)b * Ddim * Mdim + m0 + ml;
#pragma unroll 4
    for (int dd = 0; dd < 32; dd++) {
        int d = dg * 32 + dd;
        float val = base[(size_t)d * Mdim];
#pragma unroll
        for (int p = 0; p < Pdim; p++) acc[p] = fmaf(val, sw[p * Ddim + d], acc[p]);
    }
#pragma unroll
    for (int p = 0; p < Pdim; p++) part[dg][ml][p] = acc[p];
    __syncthreads();

    int m2 = tid >> 3, p2 = tid & 7;
    float sum = pb[p2];
#pragma unroll
    for (int g = 0; g < 8; g++) sum += part[g][m2][p2];
    float* dOut = which ? g_dB : g_dA;
    dOut[((size_t)b * MP + m0 + m2) * Pdim + p2] = sum;
}

// ---------------------------------------------------------------- persistent Sinkhorn

// epilogue shared by single/dual paths
__device__ __forceinline__ void row_epilogue(const MlpW* W, float tot, float t5[5],
                                             bool dust, const float* dfeat,
                                             float* fout, int m) {
    float lse = __log2f(tot) - WSCALE;
    float l2mu = dust ? -1.0f : -12.0f;
    float un = l2mu - lse;
    fout[0] = l2mu * LN2_;
    fout[1] = un * LN2_;
    fout[2] = 0.0f;
    fout[3] = __logf(__fdividef(t5[0], t5[1]));
    fout[4] = __logf(__fdividef(t5[0], t5[2]));
    fout[5] = __logf(__fdividef(t5[0], t5[3]));
    fout[6] = __logf(__fdividef(t5[0], t5[4]));
    fout[7] = __logf(__fdividef(tot, t5[0]));
    const float* da = dfeat + (size_t)m * Pdim;
#pragma unroll
    for (int p = 0; p < 8; p++) fout[8 + p] = da[p];
}

// single-row sweep + MLP (remainder / dustbin rows)
__device__ void row_work(const MlpW* W, const __half* Emat, const float* ws,
                         float EA, const float* dfeat, float* uout,
                         int m, int lane) {
    bool dust = (m == Mdim);
    const uint2* erow = reinterpret_cast<const uint2*>(Emat + (size_t)m * Ndim);
    const float4* ws4 = reinterpret_cast<const float4*>(ws);

    float s0 = 0.0f, s1 = 0.0f, s2 = 0.0f, s3 = 0.0f;
    float t5[5] = {-INFINITY, -INFINITY, -INFINITY, -INFINITY, -INFINITY};

    if (!dust) {
#pragma unroll
        for (int i = 0; i < 8; i++) {
            uint2 ea = erow[i * 64 + lane];
            uint2 eb = erow[i * 64 + 32 + lane];
            float4 wa = ws4[i * 64 + lane];
            float4 wb = ws4[i * 64 + 32 + lane];
            float2 gA = __half22float2(*reinterpret_cast<__half2*>(&ea.x));
            float2 gB = __half22float2(*reinterpret_cast<__half2*>(&ea.y));
            float2 gC = __half22float2(*reinterpret_cast<__half2*>(&eb.x));
            float2 gD = __half22float2(*reinterpret_cast<__half2*>(&eb.y));
            float p0 = gA.x * wa.x, p1 = gA.y * wa.y;
            float p2 = gB.x * wa.z, p3 = gB.y * wa.w;
            float p4 = gC.x * wb.x, p5 = gC.y * wb.y;
            float p6 = gD.x * wb.z, p7 = gD.y * wb.w;
            s0 += p0; s1 += p1; s2 += p2; s3 += p3;
            s0 += p4; s1 += p5; s2 += p6; s3 += p7;
            float gm = fmaxf(fmaxf(fmaxf(p0, p1), fmaxf(p2, p3)),
                             fmaxf(fmaxf(p4, p5), fmaxf(p6, p7)));
            ladder5(t5, gm);
        }
    } else {
#pragma unroll
        for (int i = 0; i < 8; i++) {
            float4 wa = ws4[i * 64 + lane];
            float4 wb = ws4[i * 64 + 32 + lane];
            float p0 = EA * wa.x, p1 = EA * wa.y, p2 = EA * wa.z, p3 = EA * wa.w;
            float p4 = EA * wb.x, p5 = EA * wb.y, p6 = EA * wb.z, p7 = EA * wb.w;
            s0 += p0; s1 += p1; s2 += p2; s3 += p3;
            s0 += p4; s1 += p5; s2 += p6; s3 += p7;
            float gm = fmaxf(fmaxf(fmaxf(p0, p1), fmaxf(p2, p3)),
                             fmaxf(fmaxf(p4, p5), fmaxf(p6, p7)));
            ladder5(t5, gm);
        }
    }
    if (lane == 0) {
        float p = EA * ws[Ndim];
        s0 += p;
        ladder5(t5, p);
    }

    float tot = warp_reduce_sum((s0 + s1) + (s2 + s3));
    top5_merge_shfl(t5);

    float f[16];
    row_epilogue(W, tot, t5, dust, dfeat, f, m);
    float lse = __log2f(tot) - WSCALE;
    float l2mu = dust ? -1.0f : -12.0f;
    float un = l2mu - lse;
    float delta = warp_mlp(W, f, lane);
    if (lane == 0) uout[m] = un + delta * LOG2E_;
}

// dual-row sweep + fused MLP (both rows guaranteed non-dust)
__device__ void dual_row_work(const MlpW* W, const __half* Emat, const float* ws,
                              float EA, const float* dfeat, float* uout,
                              int m0, int m1, int lane) {
    const uint2* er0 = reinterpret_cast<const uint2*>(Emat + (size_t)m0 * Ndim);
    const uint2* er1 = reinterpret_cast<const uint2*>(Emat + (size_t)m1 * Ndim);
    const float4* ws4 = reinterpret_cast<const float4*>(ws);

    float sA0 = 0.0f, sA1 = 0.0f, sB0 = 0.0f, sB1 = 0.0f;
    float tA[5], tB[5];
#pragma unroll
    for (int i = 0; i < 5; i++) { tA[i] = -INFINITY; tB[i] = -INFINITY; }

#pragma unroll
    for (int i = 0; i < 8; i++) {
        int idx0 = i * 64 + lane, idx1 = idx0 + 32;
        uint2 ea0 = er0[idx0];
        uint2 eb0 = er0[idx1];
        uint2 ea1 = er1[idx0];
        uint2 eb1 = er1[idx1];
        float4 wa = ws4[idx0];
        float4 wb = ws4[idx1];
        // row 0
        {
            float2 gA = __half22float2(*reinterpret_cast<__half2*>(&ea0.x));
            float2 gB = __half22float2(*reinterpret_cast<__half2*>(&ea0.y));
            float2 gC = __half22float2(*reinterpret_cast<__half2*>(&eb0.x));
            float2 gD = __half22float2(*reinterpret_cast<__half2*>(&eb0.y));
            float p0 = gA.x * wa.x, p1 = gA.y * wa.y;
            float p2 = gB.x * wa.z, p3 = gB.y * wa.w;
            float p4 = gC.x * wb.x, p5 = gC.y * wb.y;
            float p6 = gD.x * wb.z, p7 = gD.y * wb.w;
            sA0 += (p0 + p2) + (p4 + p6);
            sA1 += (p1 + p3) + (p5 + p7);
            float gm = fmaxf(fmaxf(fmaxf(p0, p1), fmaxf(p2, p3)),
                             fmaxf(fmaxf(p4, p5), fmaxf(p6, p7)));
            ladder5(tA, gm);
        }
        // row 1
        {
            float2 gA = __half22float2(*reinterpret_cast<__half2*>(&ea1.x));
            float2 gB = __half22float2(*reinterpret_cast<__half2*>(&ea1.y));
            float2 gC = __half22float2(*reinterpret_cast<__half2*>(&eb1.x));
            float2 gD = __half22float2(*reinterpret_cast<__half2*>(&eb1.y));
            float p0 = gA.x * wa.x, p1 = gA.y * wa.y;
            float p2 = gB.x * wa.z, p3 = gB.y * wa.w;
            float p4 = gC.x * wb.x, p5 = gC.y * wb.y;
            float p6 = gD.x * wb.z, p7 = gD.y * wb.w;
            sB0 += (p0 + p2) + (p4 + p6);
            sB1 += (p1 + p3) + (p5 + p7);
            float gm = fmaxf(fmaxf(fmaxf(p0, p1), fmaxf(p2, p3)),
                             fmaxf(fmaxf(p4, p5), fmaxf(p6, p7)));
            ladder5(tB, gm);
        }
    }
    if (lane == 0) {  // dustbin column for both rows
        float p = EA * ws[Ndim];
        sA0 += p;  ladder5(tA, p);
        sB0 += p;  ladder5(tB, p);
    }

    float tot0 = warp_reduce_sum(sA0 + sA1);
    float tot1 = warp_reduce_sum(sB0 + sB1);
    top5_merge_shfl(tA);
    top5_merge_shfl(tB);

    float f0[16], f1[16];
    row_epilogue(W, tot0, tA, false, dfeat, f0, m0);
    row_epilogue(W, tot1, tB, false, dfeat, f1, m1);
    float un0 = -12.0f - (__log2f(tot0) - WSCALE);
    float un1 = -12.0f - (__log2f(tot1) - WSCALE);

    float d0, d1;
    warp_mlp2(W, f0, f1, lane, &d0, &d1);
    if (lane == 0) {
        uout[m0] = un0 + d0 * LOG2E_;
        uout[m1] = un1 + d1 * LOG2E_;
    }
}

__global__ __launch_bounds__(256) void sink_all(
    const float* __restrict__ alpha,
    const float* rw1, const float* rb1, const float* rg1, const float* rbe1,
    const float* rw2, const float* rb2, const float* rg2, const float* rbe2,
    const float* rw3, const float* rb3,
    const float* cw1, const float* cb1, const float* cg1, const float* cbe1,
    const float* cw2, const float* cb2, const float* cg2, const float* cbe2,
    const float* cw3, const float* cb3,
    float* __restrict__ out) {
    extern __shared__ __align__(16) unsigned char smem_raw[];
    SmemAll* S = reinterpret_cast<SmemAll*>(smem_raw);

    int tid = threadIdx.x;
    int warp = tid >> 5, lane = tid & 31;
    int b = blockIdx.x & 3;          // batch bound to block
    int blk = blockIdx.x >> 2;
    int nb = gridDim.x >> 2;
    int stride = nb * 8;             // warps per batch

    load_mlp_weights(&S->Wr, rw1, rb1, rg1, rbe1, rw2, rb2, rg2, rbe2, rw3, rb3, tid, 256);
    load_mlp_weights(&S->Wc, cw1, cb1, cg1, cbe1, cw2, cb2, cg2, cbe2, cw3, cb3, tid, 256);

    float alphaL = alpha[0] * LOG2E_;
    float EA = ex2(alphaL);

    int bar = 0;
    for (int it = 0; it < 3; it++) {
#pragma unroll
        for (int axis = 0; axis < 2; axis++) {
            if (it != 0 || axis != 0) grid_barrier(bar++);
            const float* vin  = (axis == 0 ? g_v : g_u) + b * UST;
            float*       uout = (axis == 0 ? g_u : g_v) + b * UST;
            const float* dfeat = (axis == 0 ? g_dA : g_dB) + (size_t)b * MP * Pdim;
            const __half* Emat = (axis == 0 ? g_ER : g_EC) + (size_t)b * Mdim * Ndim;
            const MlpW* W = (axis == 0) ? &S->Wr : &S->Wc;

            for (int i = tid; i < UST; i += 256) S->ws[i] = ex2(vin[i] + WSCALE);
            __syncthreads();

            for (int base = blk * 8 + warp; base < MP; base += 2 * stride) {
                int m0 = base, m1 = base + stride;
                if (m1 < Mdim) {
                    dual_row_work(W, Emat, S->ws, EA, dfeat, uout, m0, m1, lane);
                } else {
                    row_work(W, Emat, S->ws, EA, dfeat, uout, m0, lane);
                    if (m1 < MP) row_work(W, Emat, S->ws, EA, dfeat, uout, m1, lane);
                }
            }
        }
    }

    // ---- output phase ----
    grid_barrier(bar++);
    for (int i = tid; i < UST; i += 256) S->ws[i] = g_v[b * UST + i];  // raw v
    __syncthreads();
    const float* sv = S->ws;

    for (int m = blk * 8 + warp; m < MP; m += stride) {
        float um = g_u[b * UST + m] + 12.0f;
        float* orow = out + ((size_t)b * MP + m) * NP;
        if (m < Mdim) {
            const uint2* erow = reinterpret_cast<const uint2*>(g_ER + ((size_t)b * Mdim + m) * Ndim);
#pragma unroll 2
            for (int i = 0; i < 8; i++) {
                uint2 ea = erow[i * 64 + lane];
                uint2 eb = erow[i * 64 + 32 + lane];
                float2 gA = __half22float2(*reinterpret_cast<__half2*>(&ea.x));
                float2 gB = __half22float2(*reinterpret_cast<__half2*>(&ea.y));
                float2 gC = __half22float2(*reinterpret_cast<__half2*>(&eb.x));
                float2 gD = __half22float2(*reinterpret_cast<__half2*>(&eb.y));
                int n0 = i * 256 + lane * 4;
                int n1 = n0 + 128;
                orow[n0 + 0] = __log2f(gA.x) + um + sv[n0 + 0];
                orow[n0 + 1] = __log2f(gA.y) + um + sv[n0 + 1];
                orow[n0 + 2] = __log2f(gB.x) + um + sv[n0 + 2];
                orow[n0 + 3] = __log2f(gB.y) + um + sv[n0 + 3];
                orow[n1 + 0] = __log2f(gC.x) + um + sv[n1 + 0];
                orow[n1 + 1] = __log2f(gC.y) + um + sv[n1 + 1];
                orow[n1 + 2] = __log2f(gD.x) + um + sv[n1 + 2];
                orow[n1 + 3] = __log2f(gD.y) + um + sv[n1 + 3];
            }
            if (lane == 0) orow[Ndim] = alphaL + um + sv[Ndim];
        } else {
            for (int k = 0; k < 65; k++) {
                int n = k * 32 + lane;
                if (n < NP) orow[n] = alphaL + um + sv[n];
            }
        }
    }
}

// ---------------------------------------------------------------- launch

extern "C" void kernel_launch(void* const* d_in, const int* in_sizes, int n_in,
                              void* d_out, int out_size) {
    const float* scores = (const float*)d_in[0];
    const float* alpha  = (const float*)d_in[1];
    const float* mdesc0 = (const float*)d_in[2];
    const float* mdesc1 = (const float*)d_in[3];
    const float* pA_w   = (const float*)d_in[4];
    const float* pA_b   = (const float*)d_in[5];
    const float* pB_w   = (const float*)d_in[6];
    const float* pB_b   = (const float*)d_in[7];
    const float* rW[10];
    const float* cW[10];
    for (int i = 0; i < 10; i++) rW[i] = (const float*)d_in[8 + i];
    for (int i = 0; i < 10; i++) cW[i] = (const float*)d_in[18 + i];
    float* out = (float*)d_out;

    init_kernel<<<17, 512>>>();
    prep_kernel<<<dim3(32, 32, Bdim), 256>>>(scores);
    proj_kernel<<<dim3(32, Bdim, 2), 512>>>(mdesc0, pA_w, pA_b, mdesc1, pB_w, pB_b);

    int smem_bytes = (int)sizeof(SmemAll);
    cudaFuncSetAttribute(sink_all, cudaFuncAttributeMaxDynamicSharedMemorySize, smem_bytes);
    int occ = 0;
    cudaOccupancyMaxActiveBlocksPerMultiprocessor(&occ, sink_all, 256, smem_bytes);
    if (occ < 1) occ = 1;
    int smcount = 0;
    cudaDeviceGetAttribute(&smcount, cudaDevAttrMultiProcessorCount, 0);
    if (smcount < 1) smcount = 148;
    int grid = (smcount * occ / 4) * 4;
    if (grid < 4) grid = 4;

    sink_all<<<grid, 256, smem_bytes>>>(alpha,
        rW[0], rW[1], rW[2], rW[3], rW[4], rW[5], rW[6], rW[7], rW[8], rW[9],
        cW[0], cW[1], cW[2], cW[3], cW[4], cW[5], cW[6], cW[7], cW[8], cW[9],
        out);
}